// round 8
// baseline (speedup 1.0000x reference)
#include <cuda_runtime.h>
#include <cuda_bf16.h>
#include <cstdint>
#include <cstddef>

// R2Ntab: B=131072, F=256, R=128, O=1
#define F_DIM 256
#define R_DIM 128
#define TILE_M 128
#define GRID_CTAS 148
#define NTHREADS 256

// ---------------- device scratch (no allocs allowed) ----------------
__device__ __align__(16) float         g_wexact[R_DIM * F_DIM];
__device__ __align__(16) __nv_bfloat16 g_wb[R_DIM * F_DIM];
__device__ float g_thresh[R_DIM];
__device__ float g_bound[R_DIM];

// ---------------- helpers ----------------
static __device__ __forceinline__ uint32_t smem_u32(const void* p) {
    uint32_t a;
    asm("{ .reg .u64 t; cvta.to.shared.u64 t, %1; cvt.u32.u64 %0, t; }" : "=r"(a) : "l"(p));
    return a;
}

static __device__ __forceinline__ void ldmatrix_x4(uint32_t& r0, uint32_t& r1,
                                                   uint32_t& r2, uint32_t& r3,
                                                   uint32_t addr) {
    asm volatile("ldmatrix.sync.aligned.m8n8.x4.shared.b16 {%0,%1,%2,%3}, [%4];"
                 : "=r"(r0), "=r"(r1), "=r"(r2), "=r"(r3) : "r"(addr));
}

static __device__ __forceinline__ void mma_bf16(float* c, uint32_t a0, uint32_t a1,
                                                uint32_t a2, uint32_t a3,
                                                uint32_t b0, uint32_t b1) {
    asm volatile(
        "mma.sync.aligned.m16n8k16.row.col.f32.bf16.bf16.f32 "
        "{%0,%1,%2,%3}, {%4,%5,%6,%7}, {%8,%9}, {%0,%1,%2,%3};"
        : "+f"(c[0]), "+f"(c[1]), "+f"(c[2]), "+f"(c[3])
        : "r"(a0), "r"(a1), "r"(a2), "r"(a3), "r"(b0), "r"(b1));
}

// ---------------- SMEM layout ----------------
static constexpr int A0_OFF   = 0;
static constexpr int A_BYTES  = TILE_M * F_DIM * 2;    // 65536
static constexpr int A1_OFF   = A0_OFF + A_BYTES;
static constexpr int B_OFF    = A1_OFF + A_BYTES;      // 131072
static constexpr int B_BYTES  = R_DIM * F_DIM * 2;     // 65536
static constexpr int PART_OFF = B_OFF + B_BYTES;       // 196608
static constexpr int TH_OFF   = PART_OFF + 2 * TILE_M * 4 * 4;   // 200704
static constexpr int BND_OFF  = TH_OFF + R_DIM * 4;              // 201216
static constexpr int SMEM_TOTAL = BND_OFF + R_DIM * 4;           // 201728

// ---------------- precompute (parallel) ----------------
__global__ void r2ntab_prep(const float* __restrict__ w_cancel,
                            const float* __restrict__ w_and,
                            const float* __restrict__ b_and,
                            const float* __restrict__ w_or) {
    __shared__ float s_relu[4], s_abs[4];
    const int r = blockIdx.x;
    const int t = threadIdx.x;
    float relu = 0.0f, absr = 0.0f;
    #pragma unroll
    for (int k = 0; k < 2; k++) {
        int f = t + 128 * k;
        float w = (w_cancel[f] < 0.0f) ? 0.0f : w_and[r * F_DIM + f];
        g_wexact[r * F_DIM + f] = w;
        g_wb[r * F_DIM + f] = __float2bfloat16(w);
        relu += fmaxf(w, 0.0f);
        absr += fabsf(w);
    }
    #pragma unroll
    for (int s = 16; s > 0; s >>= 1) {
        relu += __shfl_xor_sync(0xffffffffu, relu, s);
        absr += __shfl_xor_sync(0xffffffffu, absr, s);
    }
    if ((t & 31) == 0) { s_relu[t >> 5] = relu; s_abs[t >> 5] = absr; }
    __syncthreads();
    if (t == 0) {
        float rs = s_relu[0] + s_relu[1] + s_relu[2] + s_relu[3];
        float as = s_abs[0] + s_abs[1] + s_abs[2] + s_abs[3];
        if (w_or[r] > 0.0f) {
            g_thresh[r] = 0.999999f - b_and[r] + rs;
            g_bound[r]  = as * 0.00390625f + 5e-4f;
        } else {
            g_thresh[r] = __int_as_float(0x7f800000);
            g_bound[r]  = 0.0f;
        }
    }
}

// ---------------- first-tile loader ----------------
static __device__ __forceinline__ void load_tile(const float* __restrict__ x,
                                                 int tile, char* __restrict__ abase,
                                                 int tid) {
    const float4* xp = reinterpret_cast<const float4*>(x) + (size_t)tile * TILE_M * (F_DIM / 4);
    #pragma unroll 8
    for (int i = tid; i < TILE_M * (F_DIM / 4); i += NTHREADS) {
        int row = i >> 6;
        int q   = i & 63;
        float4 v = xp[i];
        __nv_bfloat162 p0 = __floats2bfloat162_rn(v.x, v.y);
        __nv_bfloat162 p1 = __floats2bfloat162_rn(v.z, v.w);
        uint32_t u    = (uint32_t)(q >> 1);
        uint32_t off  = (uint32_t)row * 512u + ((u ^ (row & 7)) << 4) + ((q & 1) << 3);
        uint2 val;
        val.x = *reinterpret_cast<uint32_t*>(&p0);
        val.y = *reinterpret_cast<uint32_t*>(&p1);
        *reinterpret_cast<uint2*>(abase + off) = val;
    }
}

// exact fp32 recheck for near-threshold elements (guaranteed-correct slow path)
static __device__ __noinline__ int exact_check(const float* __restrict__ x,
                                               int g_row, int rule) {
    const float4* xr = reinterpret_cast<const float4*>(x + (size_t)g_row * F_DIM);
    const float4* wr = reinterpret_cast<const float4*>(g_wexact + rule * F_DIM);
    float s = 0.0f;
    #pragma unroll 8
    for (int i = 0; i < F_DIM / 4; i++) {
        float4 a = xr[i], b = wr[i];
        s += a.x * b.x + a.y * b.y + a.z * b.z + a.w * b.w;
    }
    return s > g_thresh[rule] ? 1 : 0;
}

// ---------------- main persistent kernel: 256 threads, warp tile 64x32, B in regs ----
__global__ void __launch_bounds__(NTHREADS, 1)
r2ntab_main(const float* __restrict__ x, const float* __restrict__ b_or,
            float* __restrict__ out, int num_tiles) {
    extern __shared__ char smem[];
    const uint32_t sbase = smem_u32(smem);
    const int tid  = threadIdx.x;
    const int lane = tid & 31;
    const int wid  = tid >> 5;     // 0..7
    const int wm   = wid >> 2;     // 0..1 : M group (64 rows)
    const int wn   = wid & 3;      // 0..3 : N group (32 rules)

    // ---- stage B (rules) + thresholds into smem, once ----
    {
        const uint4* wb4 = reinterpret_cast<const uint4*>(g_wb);
        #pragma unroll 4
        for (int i = tid; i < R_DIM * (F_DIM / 8); i += NTHREADS) {
            int r = i >> 5;
            int u = i & 31;
            uint4 v = wb4[i];
            uint32_t off = (uint32_t)r * 512u + (((uint32_t)u ^ (r & 7)) << 4);
            *reinterpret_cast<uint4*>(smem + B_OFF + off) = v;
        }
        if (tid < R_DIM) {
            reinterpret_cast<float*>(smem + TH_OFF)[tid]  = g_thresh[tid];
            reinterpret_cast<float*>(smem + BND_OFF)[tid] = g_bound[tid];
        }
    }
    const float bor0 = b_or[0];
    const float* th_s  = reinterpret_cast<const float*>(smem + TH_OFF);
    const float* bnd_s = reinterpret_cast<const float*>(smem + BND_OFF);
    const int rule_base = wn * 32 + (lane & 3) * 2;

    // ---- ldmatrix lane-address precompute ----
    const int idx = lane >> 3;
    const int s3  = lane & 7;
    uint32_t a_row[4];
    #pragma unroll
    for (int mt = 0; mt < 4; mt++)
        a_row[mt] = (uint32_t)(wm * 64 + mt * 16 + (idx & 1) * 8 + s3) * 512u;
    const uint32_t a_usel = (uint32_t)(idx >> 1);

    int* part = reinterpret_cast<int*>(smem + PART_OFF);   // [2][128][4]

    // loader invariants: i = tid + 256*j -> row = (tid>>6) + 4*j, q = tid&63
    const int q_l    = tid & 63;
    const int row0_l = tid >> 6;                 // 0..3
    const uint32_t u_l = (uint32_t)(q_l >> 1);
    const uint32_t halfoff_l = ((uint32_t)(q_l & 1)) << 3;

    __syncthreads();   // B staged

    // ---- load ALL B fragments into registers, once ----
    uint32_t bfr[16][4][2];
    {
        uint32_t b_row[4];
        #pragma unroll
        for (int nt = 0; nt < 4; nt++)
            b_row[nt] = sbase + B_OFF + (uint32_t)(wn * 32 + nt * 8 + s3) * 512u;
        const uint32_t b_usel = (uint32_t)(idx & 1);
        #pragma unroll
        for (int kt = 0; kt < 16; kt++) {
            uint32_t ub = 2 * kt + b_usel;
            #pragma unroll
            for (int p = 0; p < 2; p++) {
                uint32_t addr = b_row[2 * p + (idx >> 1)] + ((ub ^ s3) << 4);
                ldmatrix_x4(bfr[kt][2 * p][0], bfr[kt][2 * p][1],
                            bfr[kt][2 * p + 1][0], bfr[kt][2 * p + 1][1], addr);
            }
        }
    }

    const int t0 = blockIdx.x;
    int cur = 0;
    if (t0 < num_tiles) load_tile(x, t0, smem + A0_OFF, tid);
    __syncthreads();

    int it = 0;
    for (int t = t0; t < num_tiles; t += GRID_CTAS, it++) {
        const int tn = t + GRID_CTAS;
        const bool has_next = (tn < num_tiles);
        const float4* xn = reinterpret_cast<const float4*>(x) +
                           (size_t)tn * TILE_M * (F_DIM / 4);
        char* nbuf = smem + (cur ? A0_OFF : A1_OFF);

        // gmem loader: 16 groups of 2 float4/thread; 2 groups (4 LDG.128) in flight
        float4 buf[2][2];
        if (has_next) {
            #pragma unroll
            for (int jj = 0; jj < 2; jj++) buf[0][jj] = xn[tid + NTHREADS * jj];
            #pragma unroll
            for (int jj = 0; jj < 2; jj++) buf[1][jj] = xn[tid + NTHREADS * (2 + jj)];
        }

        const uint32_t abuf = sbase + (cur ? A1_OFF : A0_OFF);
        float acc[4][4][4];
        #pragma unroll
        for (int mt = 0; mt < 4; mt++)
            #pragma unroll
            for (int nt = 0; nt < 4; nt++)
                #pragma unroll
                for (int c = 0; c < 4; c++) acc[mt][nt][c] = 0.0f;

        // ---- k-loop: A ldmatrix + 16 resident-B mmas per k-step ----
        #pragma unroll
        for (int kt = 0; kt < 16; kt++) {
            uint32_t af[4][4];
            uint32_t ua = 2 * kt + a_usel;
            #pragma unroll
            for (int mt = 0; mt < 4; mt++) {
                uint32_t addr = abuf + a_row[mt] + ((ua ^ s3) << 4);
                ldmatrix_x4(af[mt][0], af[mt][1], af[mt][2], af[mt][3], addr);
            }
            #pragma unroll
            for (int mt = 0; mt < 4; mt++)
                #pragma unroll
                for (int nt = 0; nt < 4; nt++)
                    mma_bf16(acc[mt][nt], af[mt][0], af[mt][1], af[mt][2], af[mt][3],
                             bfr[kt][nt][0], bfr[kt][nt][1]);

            // drain arrived group kt, issue group kt+2
            if (has_next) {
                const int g = kt;                 // 0..15
                #pragma unroll
                for (int jj = 0; jj < 2; jj++) {
                    const int j   = 2 * g + jj;
                    const int row = row0_l + 4 * j;
                    float4 v = buf[g & 1][jj];
                    __nv_bfloat162 p0 = __floats2bfloat162_rn(v.x, v.y);
                    __nv_bfloat162 p1 = __floats2bfloat162_rn(v.z, v.w);
                    uint32_t off = (uint32_t)row * 512u +
                                   ((u_l ^ (uint32_t)(row & 7)) << 4) + halfoff_l;
                    uint2 val;
                    val.x = *reinterpret_cast<uint32_t*>(&p0);
                    val.y = *reinterpret_cast<uint32_t*>(&p1);
                    *reinterpret_cast<uint2*>(nbuf + off) = val;
                }
                if (g < 14) {
                    #pragma unroll
                    for (int jj = 0; jj < 2; jj++)
                        buf[g & 1][jj] = xn[tid + NTHREADS * (2 * (g + 2) + jj)];
                }
            }
        }

        // ---- epilogue: threshold-count with exact-recheck guard ----
        const int par = it & 1;
        #pragma unroll
        for (int mt = 0; mt < 4; mt++) {
            int rA = wm * 64 + mt * 16 + (lane >> 2);
            int rB = rA + 8;
            int cA = 0, cB = 0;
            #pragma unroll
            for (int nt = 0; nt < 4; nt++) {
                #pragma unroll
                for (int c = 0; c < 2; c++) {
                    const int rule = rule_base + nt * 8 + c;
                    const float thv  = th_s[rule];
                    const float bndv = bnd_s[rule];
                    float dA = acc[mt][nt][c] - thv;
                    float dB = acc[mt][nt][c + 2] - thv;
                    if (fabsf(dA) <= bndv)
                        cA += exact_check(x, t * TILE_M + rA, rule);
                    else
                        cA += (dA > 0.0f) ? 1 : 0;
                    if (fabsf(dB) <= bndv)
                        cB += exact_check(x, t * TILE_M + rB, rule);
                    else
                        cB += (dB > 0.0f) ? 1 : 0;
                }
            }
            cA += __shfl_xor_sync(0xffffffffu, cA, 1);
            cA += __shfl_xor_sync(0xffffffffu, cA, 2);
            cB += __shfl_xor_sync(0xffffffffu, cB, 1);
            cB += __shfl_xor_sync(0xffffffffu, cB, 2);
            if ((lane & 3) == 0) {
                part[par * 512 + rA * 4 + wn] = cA;
                part[par * 512 + rB * 4 + wn] = cB;
            }
        }
        __syncthreads();   // partials ready; next-tile STS complete

        if (tid < TILE_M) {
            int4 qv = *reinterpret_cast<int4*>(&part[par * 512 + tid * 4]);
            out[t * TILE_M + tid] = (float)(qv.x + qv.y + qv.z + qv.w) + bor0;
        }
        cur ^= 1;
    }
}

extern "C" void kernel_launch(void* const* d_in, const int* in_sizes, int n_in,
                              void* d_out, int out_size) {
    const float* x        = (const float*)d_in[0];
    const float* w_cancel = (const float*)d_in[1];
    const float* w_and    = (const float*)d_in[2];
    const float* b_and    = (const float*)d_in[3];
    const float* w_or     = (const float*)d_in[4];
    const float* b_or     = (const float*)d_in[5];
    float* out = (float*)d_out;

    const int B_total   = in_sizes[0] / F_DIM;   // 131072
    const int num_tiles = B_total / TILE_M;      // 1024

    cudaFuncSetAttribute(r2ntab_main, cudaFuncAttributeMaxDynamicSharedMemorySize, SMEM_TOTAL);

    r2ntab_prep<<<R_DIM, 128>>>(w_cancel, w_and, b_and, w_or);
    r2ntab_main<<<GRID_CTAS, NTHREADS, SMEM_TOTAL>>>(x, b_or, out, num_tiles);
    (void)n_in; (void)out_size;
}

// round 12
// speedup vs baseline: 1.0279x; 1.0279x over previous
#include <cuda_runtime.h>
#include <cstdint>
#include <cstddef>

// R2Ntab: B=131072, F=256, R=128, O=1
#define F_DIM 256
#define R_DIM 128
#define TILE_M 128
#define GRID_CTAS 148
#define NTHREADS 512

// ---------------- device scratch (no allocs allowed) ----------------
__device__ __align__(16) float       g_wexact[R_DIM * F_DIM]; // exact masked weights
__device__ __align__(16) signed char g_wq[R_DIM * F_DIM];     // int8 quantized weights [r][f]
__device__ float g_thresh[R_DIM];  // fires iff idot*scale > thresh
__device__ float g_scale[R_DIM];   // per-rule quant scale
__device__ float g_bound[R_DIM];   // guaranteed |idot*scale - exact| bound

// ---------------- helpers ----------------
static __device__ __forceinline__ uint32_t smem_u32(const void* p) {
    uint32_t a;
    asm("{ .reg .u64 t; cvta.to.shared.u64 t, %1; cvt.u32.u64 %0, t; }" : "=r"(a) : "l"(p));
    return a;
}

static __device__ __forceinline__ void ldmatrix_x4(uint32_t& r0, uint32_t& r1,
                                                   uint32_t& r2, uint32_t& r3,
                                                   uint32_t addr) {
    asm volatile("ldmatrix.sync.aligned.m8n8.x4.shared.b16 {%0,%1,%2,%3}, [%4];"
                 : "=r"(r0), "=r"(r1), "=r"(r2), "=r"(r3) : "r"(addr));
}

static __device__ __forceinline__ void mma_s8(int* c, uint32_t a0, uint32_t a1,
                                              uint32_t a2, uint32_t a3,
                                              uint32_t b0, uint32_t b1) {
    asm volatile(
        "mma.sync.aligned.m16n8k32.row.col.s32.s8.s8.s32 "
        "{%0,%1,%2,%3}, {%4,%5,%6,%7}, {%8,%9}, {%0,%1,%2,%3};"
        : "+r"(c[0]), "+r"(c[1]), "+r"(c[2]), "+r"(c[3])
        : "r"(a0), "r"(a1), "r"(a2), "r"(a3), "r"(b0), "r"(b1));
}

// 4 floats (each exactly 0.0f or 1.0f) -> packed s8x4 {0,1}
static __device__ __forceinline__ uint32_t pack4(float4 v) {
    uint32_t b0 = __float_as_uint(v.x), b1 = __float_as_uint(v.y);
    uint32_t b2 = __float_as_uint(v.z), b3 = __float_as_uint(v.w);
    uint32_t r01 = __byte_perm(b0, b1, 0x0073);   // [f0.b3, f1.b3, 0, 0]
    uint32_t r23 = __byte_perm(b2, b3, 0x0073);
    return __byte_perm(r01, r23, 0x5410) & 0x01010101u;  // 0x3F&1=1, 0x00&1=0
}

// ---------------- SMEM layout ----------------
// A tiles (s8): 128 rows x 256B, 16B unit u' = u ^ (row&7)
static constexpr int A0_OFF   = 0;
static constexpr int A_BYTES  = TILE_M * F_DIM;        // 32768
static constexpr int A1_OFF   = A0_OFF + A_BYTES;      // 32768
static constexpr int B_OFF    = A1_OFF + A_BYTES;      // 65536
static constexpr int B_BYTES  = R_DIM * F_DIM;         // 32768
static constexpr int PART_OFF = B_OFF + B_BYTES;       // 98304  [2][128][4] ints
static constexpr int TH_OFF   = PART_OFF + 2 * TILE_M * 4 * 4;   // 102400
static constexpr int SC_OFF   = TH_OFF + R_DIM * 4;              // 102912
static constexpr int BND_OFF  = SC_OFF + R_DIM * 4;              // 103424
static constexpr int SMEM_TOTAL = BND_OFF + R_DIM * 4;           // 103936

// ---------------- precompute: mask, quantize, thresholds, bounds ----------------
__global__ void r2ntab_prep(const float* __restrict__ w_cancel,
                            const float* __restrict__ w_and,
                            const float* __restrict__ b_and,
                            const float* __restrict__ w_or) {
    __shared__ float s_relu[4], s_max[4], s_err[4];
    __shared__ float sh_scale;
    const int r = blockIdx.x;
    const int t = threadIdx.x;          // 0..127
    float w0, w1;
    {
        int f0 = t, f1 = t + 128;
        w0 = (w_cancel[f0] < 0.0f) ? 0.0f : w_and[r * F_DIM + f0];
        w1 = (w_cancel[f1] < 0.0f) ? 0.0f : w_and[r * F_DIM + f1];
        g_wexact[r * F_DIM + f0] = w0;
        g_wexact[r * F_DIM + f1] = w1;
    }
    float relu = fmaxf(w0, 0.0f) + fmaxf(w1, 0.0f);
    float mx   = fmaxf(fabsf(w0), fabsf(w1));
    #pragma unroll
    for (int s = 16; s > 0; s >>= 1) {
        relu += __shfl_xor_sync(0xffffffffu, relu, s);
        mx    = fmaxf(mx, __shfl_xor_sync(0xffffffffu, mx, s));
    }
    if ((t & 31) == 0) { s_relu[t >> 5] = relu; s_max[t >> 5] = mx; }
    __syncthreads();
    if (t == 0) {
        float ma = fmaxf(fmaxf(s_max[0], s_max[1]), fmaxf(s_max[2], s_max[3]));
        sh_scale = (ma > 0.0f) ? (ma / 127.0f) : 1.0f;
    }
    __syncthreads();
    const float sc = sh_scale;
    // quantize + per-feature error
    int q0 = __float2int_rn(w0 / sc);
    int q1 = __float2int_rn(w1 / sc);
    g_wq[r * F_DIM + t]       = (signed char)q0;
    g_wq[r * F_DIM + t + 128] = (signed char)q1;
    float err = fabsf(w0 - sc * (float)q0) + fabsf(w1 - sc * (float)q1);
    #pragma unroll
    for (int s = 16; s > 0; s >>= 1)
        err += __shfl_xor_sync(0xffffffffu, err, s);
    if ((t & 31) == 0) s_err[t >> 5] = err;
    __syncthreads();
    if (t == 0) {
        float rs = s_relu[0] + s_relu[1] + s_relu[2] + s_relu[3];
        float es = s_err[0] + s_err[1] + s_err[2] + s_err[3];
        if (w_or[r] > 0.0f) {
            g_thresh[r] = 0.999999f - b_and[r] + rs;
            g_scale[r]  = sc;
            g_bound[r]  = es + 1e-4f;
        } else {
            g_thresh[r] = __int_as_float(0x7f800000);  // +inf: never fires
            g_scale[r]  = sc;
            g_bound[r]  = 0.0f;
        }
    }
}

// ---------------- first-tile loader: fp32 -> packed s8 swizzled smem ----------------
static __device__ __forceinline__ void load_tile(const float* __restrict__ x,
                                                 int tile, char* __restrict__ abase,
                                                 int tid) {
    const float4* xp = reinterpret_cast<const float4*>(x) + (size_t)tile * TILE_M * (F_DIM / 4);
    #pragma unroll 8
    for (int i = tid; i < TILE_M * (F_DIM / 4); i += NTHREADS) {
        int row = i >> 6;          // 0..127
        int q   = i & 63;          // float4 index -> s8 bytes 4q..4q+3
        uint32_t val = pack4(xp[i]);
        uint32_t off = (uint32_t)row * 256u +
                       ((((uint32_t)(q >> 2)) ^ (row & 7)) << 4) + ((q & 3) << 2);
        *reinterpret_cast<uint32_t*>(abase + off) = val;
    }
}

// exact fp32 recheck (guaranteed-correct slow path, ~0 hits/run)
static __device__ __noinline__ int exact_check(const float* __restrict__ x,
                                               int g_row, int rule) {
    const float4* xr = reinterpret_cast<const float4*>(x + (size_t)g_row * F_DIM);
    const float4* wr = reinterpret_cast<const float4*>(g_wexact + rule * F_DIM);
    float s = 0.0f;
    #pragma unroll 8
    for (int i = 0; i < F_DIM / 4; i++) {
        float4 a = xr[i], b = wr[i];
        s += a.x * b.x + a.y * b.y + a.z * b.z + a.w * b.w;
    }
    return s > g_thresh[rule] ? 1 : 0;
}

// ---------------- main persistent kernel: 512 threads, warp tile 32x32, IMMA ----------
__global__ void __launch_bounds__(NTHREADS, 1)
r2ntab_main(const float* __restrict__ x, const float* __restrict__ b_or,
            float* __restrict__ out, int num_tiles) {
    extern __shared__ char smem[];
    const uint32_t sbase = smem_u32(smem);
    const int tid  = threadIdx.x;
    const int lane = tid & 31;
    const int wid  = tid >> 5;     // 0..15
    const int wm   = wid >> 2;     // 0..3 : M group (32 rows)
    const int wn   = wid & 3;      // 0..3 : N group (32 rules)

    // ---- stage B (int8 rules) + epilogue tables into smem, once ----
    {
        const uint4* wq4 = reinterpret_cast<const uint4*>(g_wq);
        #pragma unroll 4
        for (int i = tid; i < R_DIM * (F_DIM / 16); i += NTHREADS) {  // 2048 16B units
            int r = i >> 4;
            int u = i & 15;
            uint4 v = wq4[i];
            uint32_t off = (uint32_t)r * 256u + (((uint32_t)u ^ (r & 7)) << 4);
            *reinterpret_cast<uint4*>(smem + B_OFF + off) = v;
        }
        if (tid < R_DIM) {
            reinterpret_cast<float*>(smem + TH_OFF)[tid]  = g_thresh[tid];
            reinterpret_cast<float*>(smem + SC_OFF)[tid]  = g_scale[tid];
            reinterpret_cast<float*>(smem + BND_OFF)[tid] = g_bound[tid];
        }
    }
    const float bor0 = b_or[0];
    const float* th_s  = reinterpret_cast<const float*>(smem + TH_OFF);
    const float* sc_s  = reinterpret_cast<const float*>(smem + SC_OFF);
    const float* bnd_s = reinterpret_cast<const float*>(smem + BND_OFF);
    const int rule_base = wn * 32 + (lane & 3) * 2;

    // ---- ldmatrix lane-address precompute (swizzle key == s3 for all rows) ----
    const int idx = lane >> 3;
    const int s3  = lane & 7;
    // A: matrices (r0-7,c0),(r8-15,c0),(r0-7,c1),(r8-15,c1)
    uint32_t a_base[2];
    #pragma unroll
    for (int mt = 0; mt < 2; mt++)
        a_base[mt] = (uint32_t)(wm * 32 + mt * 16 + (idx & 1) * 8 + s3) * 256u;
    const uint32_t a_uoff = (uint32_t)(idx >> 1);
    // B: matrices (n0-7,c0),(n0-7,c1),(n8-15,c0),(n8-15,c1)
    uint32_t b_base[2];
    #pragma unroll
    for (int p = 0; p < 2; p++)
        b_base[p] = sbase + B_OFF +
                    (uint32_t)(wn * 32 + p * 16 + (idx >> 1) * 8 + s3) * 256u;
    const uint32_t b_uoff = (uint32_t)(idx & 1);

    int* part = reinterpret_cast<int*>(smem + PART_OFF);   // [2][128][4]

    // loader invariants: i = tid + 512*j -> row = (tid>>6) + 8*j, q = tid&63
    const int q_l    = tid & 63;
    const int row0_l = tid >> 6;                 // 0..7  (== row&7 for all j)
    const uint32_t st_const = ((((uint32_t)(q_l >> 2)) ^ (uint32_t)row0_l) << 4) +
                              ((uint32_t)(q_l & 3) << 2);

    const int t0 = blockIdx.x;
    int cur = 0;
    if (t0 < num_tiles) load_tile(x, t0, smem + A0_OFF, tid);
    __syncthreads();

    int it = 0;
    for (int t = t0; t < num_tiles; t += GRID_CTAS, it++) {
        const int tn = t + GRID_CTAS;
        const bool has_next = (tn < num_tiles);
        const float4* xn = reinterpret_cast<const float4*>(x) +
                           (size_t)tn * TILE_M * (F_DIM / 4);
        char* nbuf = smem + (cur ? A0_OFF : A1_OFF);

        // gmem loader: 4 groups of 4 float4/thread; 2 groups (8 LDG.128) in flight
        float4 buf[2][4];
        if (has_next) {
            #pragma unroll
            for (int jj = 0; jj < 4; jj++) buf[0][jj] = xn[tid + NTHREADS * jj];
            #pragma unroll
            for (int jj = 0; jj < 4; jj++) buf[1][jj] = xn[tid + NTHREADS * (4 + jj)];
        }

        const uint32_t abuf = sbase + (cur ? A1_OFF : A0_OFF);
        int acc[2][4][4];
        #pragma unroll
        for (int mt = 0; mt < 2; mt++)
            #pragma unroll
            for (int nt = 0; nt < 4; nt++)
                #pragma unroll
                for (int c = 0; c < 4; c++) acc[mt][nt][c] = 0;

        // ---- k-loop: 8 k-steps of 32 features ----
        #pragma unroll
        for (int kt = 0; kt < 8; kt++) {
            uint32_t bf[4][2];
            #pragma unroll
            for (int p = 0; p < 2; p++) {
                uint32_t addr = b_base[p] + (((2 * kt + b_uoff) ^ s3) << 4);
                ldmatrix_x4(bf[2 * p][0], bf[2 * p][1], bf[2 * p + 1][0], bf[2 * p + 1][1],
                            addr);
            }
            #pragma unroll
            for (int mt = 0; mt < 2; mt++) {
                uint32_t a0, a1, a2, a3;
                uint32_t addr = abuf + a_base[mt] + (((2 * kt + a_uoff) ^ s3) << 4);
                ldmatrix_x4(a0, a1, a2, a3, addr);
                #pragma unroll
                for (int nt = 0; nt < 4; nt++)
                    mma_s8(acc[mt][nt], a0, a1, a2, a3, bf[nt][0], bf[nt][1]);
            }

            // odd k-steps: drain arrived group g, issue group g+2
            if ((kt & 1) == 1 && has_next) {
                const int g = kt >> 1;            // 0..3
                #pragma unroll
                for (int jj = 0; jj < 4; jj++) {
                    const int j   = 4 * g + jj;
                    const int row = row0_l + 8 * j;
                    uint32_t val = pack4(buf[g & 1][jj]);
                    *reinterpret_cast<uint32_t*>(nbuf + (uint32_t)row * 256u + st_const) = val;
                }
                if (g < 2) {
                    #pragma unroll
                    for (int jj = 0; jj < 4; jj++)
                        buf[g & 1][jj] = xn[tid + NTHREADS * (4 * (g + 2) + jj)];
                }
            }
        }

        // ---- epilogue: threshold-count with exact-recheck guard ----
        const int par = it & 1;
        #pragma unroll
        for (int mt = 0; mt < 2; mt++) {
            int rA = wm * 32 + mt * 16 + (lane >> 2);
            int rB = rA + 8;
            int cA = 0, cB = 0;
            #pragma unroll
            for (int nt = 0; nt < 4; nt++) {
                #pragma unroll
                for (int c = 0; c < 2; c++) {
                    const int rule = rule_base + nt * 8 + c;
                    const float thv  = th_s[rule];
                    const float scv  = sc_s[rule];
                    const float bndv = bnd_s[rule];
                    float dA = (float)acc[mt][nt][c]     * scv - thv;
                    float dB = (float)acc[mt][nt][c + 2] * scv - thv;
                    if (fabsf(dA) <= bndv)
                        cA += exact_check(x, t * TILE_M + rA, rule);
                    else
                        cA += (dA > 0.0f) ? 1 : 0;
                    if (fabsf(dB) <= bndv)
                        cB += exact_check(x, t * TILE_M + rB, rule);
                    else
                        cB += (dB > 0.0f) ? 1 : 0;
                }
            }
            cA += __shfl_xor_sync(0xffffffffu, cA, 1);
            cA += __shfl_xor_sync(0xffffffffu, cA, 2);
            cB += __shfl_xor_sync(0xffffffffu, cB, 1);
            cB += __shfl_xor_sync(0xffffffffu, cB, 2);
            if ((lane & 3) == 0) {
                part[par * 512 + rA * 4 + wn] = cA;
                part[par * 512 + rB * 4 + wn] = cB;
            }
        }
        __syncthreads();   // partials ready; next-tile STS complete

        if (tid < TILE_M) {
            int4 qv = *reinterpret_cast<int4*>(&part[par * 512 + tid * 4]);
            out[t * TILE_M + tid] = (float)(qv.x + qv.y + qv.z + qv.w) + bor0;
        }
        cur ^= 1;
        // parity ping-pong on `part`: this parity isn't rewritten until 2 barriers later.
    }
}

extern "C" void kernel_launch(void* const* d_in, const int* in_sizes, int n_in,
                              void* d_out, int out_size) {
    const float* x        = (const float*)d_in[0];
    const float* w_cancel = (const float*)d_in[1];
    const float* w_and    = (const float*)d_in[2];
    const float* b_and    = (const float*)d_in[3];
    const float* w_or     = (const float*)d_in[4];
    const float* b_or     = (const float*)d_in[5];
    float* out = (float*)d_out;

    const int B_total   = in_sizes[0] / F_DIM;   // 131072
    const int num_tiles = B_total / TILE_M;      // 1024

    cudaFuncSetAttribute(r2ntab_main, cudaFuncAttributeMaxDynamicSharedMemorySize, SMEM_TOTAL);

    r2ntab_prep<<<R_DIM, 128>>>(w_cancel, w_and, b_and, w_or);
    r2ntab_main<<<GRID_CTAS, NTHREADS, SMEM_TOTAL>>>(x, b_or, out, num_tiles);
    (void)n_in; (void)out_size;
}

// round 13
// speedup vs baseline: 1.1404x; 1.1095x over previous
#include <cuda_runtime.h>
#include <cuda_fp16.h>
#include <cstdint>
#include <cstddef>

// R2Ntab: B=131072, F=256, R=128, O=1
#define F_DIM 256
#define R_DIM 128
#define TILE_M 128
#define NCTAS 296          // 2 CTAs per SM x 148
#define NTHREADS 256

// ---------------- device scratch (no allocs allowed) ----------------
__device__ __align__(16) float  g_wexact[R_DIM * F_DIM]; // exact masked weights
__device__ __align__(16) __half g_wh[R_DIM * F_DIM];     // f16 masked weights [r][f]
__device__ float g_thresh[R_DIM];  // fires iff dot > thresh (inf if OR-gate off)
__device__ float g_bound[R_DIM];   // guaranteed |f16dot - exact| bound

// ---------------- helpers ----------------
static __device__ __forceinline__ uint32_t smem_u32(const void* p) {
    uint32_t a;
    asm("{ .reg .u64 t; cvta.to.shared.u64 t, %1; cvt.u32.u64 %0, t; }" : "=r"(a) : "l"(p));
    return a;
}

static __device__ __forceinline__ void ldmatrix_x4(uint32_t& r0, uint32_t& r1,
                                                   uint32_t& r2, uint32_t& r3,
                                                   uint32_t addr) {
    asm volatile("ldmatrix.sync.aligned.m8n8.x4.shared.b16 {%0,%1,%2,%3}, [%4];"
                 : "=r"(r0), "=r"(r1), "=r"(r2), "=r"(r3) : "r"(addr));
}

// f16-accumulate HMMA: D(2 regs of half2) = A*B + D
static __device__ __forceinline__ void mma_f16(uint32_t* d, uint32_t a0, uint32_t a1,
                                               uint32_t a2, uint32_t a3,
                                               uint32_t b0, uint32_t b1) {
    asm volatile(
        "mma.sync.aligned.m16n8k16.row.col.f16.f16.f16.f16 "
        "{%0,%1}, {%2,%3,%4,%5}, {%6,%7}, {%0,%1};"
        : "+r"(d[0]), "+r"(d[1])
        : "r"(a0), "r"(a1), "r"(a2), "r"(a3), "r"(b0), "r"(b1));
}

// ---------------- SMEM layout (fits 2 CTAs/SM) ----------------
// A ring: 2 slots x (128 rows x 128B)  (K=64 f16 chunk, SW128: u' = u ^ (row&7))
static constexpr int RING_OFF   = 0;
static constexpr int SLOT_BYTES = TILE_M * 128;            // 16384
static constexpr int B_OFF      = RING_OFF + 2 * SLOT_BYTES;  // 32768
static constexpr int B_BYTES    = R_DIM * F_DIM * 2;       // 65536 (512B rows)
static constexpr int PART_OFF   = B_OFF + B_BYTES;         // 98304  [2][128][4] ints
static constexpr int TH_OFF     = PART_OFF + 2 * TILE_M * 4 * 4;  // 102400
static constexpr int BND_OFF    = TH_OFF + R_DIM * 4;             // 102912
static constexpr int SMEM_TOTAL = BND_OFF + R_DIM * 4;            // 103424

// ---------------- precompute: mask, f16 weights, thresholds, bounds ----------------
__global__ void r2ntab_prep(const float* __restrict__ w_cancel,
                            const float* __restrict__ w_and,
                            const float* __restrict__ b_and,
                            const float* __restrict__ w_or) {
    __shared__ float s_relu[4], s_err[4], s_abs[4];
    const int r = blockIdx.x;
    const int t = threadIdx.x;          // 0..127
    float w0, w1;
    {
        int f0 = t, f1 = t + 128;
        w0 = (w_cancel[f0] < 0.0f) ? 0.0f : w_and[r * F_DIM + f0];
        w1 = (w_cancel[f1] < 0.0f) ? 0.0f : w_and[r * F_DIM + f1];
        g_wexact[r * F_DIM + f0] = w0;
        g_wexact[r * F_DIM + f1] = w1;
    }
    __half h0 = __float2half_rn(w0), h1 = __float2half_rn(w1);
    g_wh[r * F_DIM + t]       = h0;
    g_wh[r * F_DIM + t + 128] = h1;
    float relu = fmaxf(w0, 0.0f) + fmaxf(w1, 0.0f);
    float err  = fabsf(w0 - __half2float(h0)) + fabsf(w1 - __half2float(h1));
    float absh = fabsf(__half2float(h0)) + fabsf(__half2float(h1));
    #pragma unroll
    for (int s = 16; s > 0; s >>= 1) {
        relu += __shfl_xor_sync(0xffffffffu, relu, s);
        err  += __shfl_xor_sync(0xffffffffu, err, s);
        absh += __shfl_xor_sync(0xffffffffu, absh, s);
    }
    if ((t & 31) == 0) { s_relu[t >> 5] = relu; s_err[t >> 5] = err; s_abs[t >> 5] = absh; }
    __syncthreads();
    if (t == 0) {
        float rs = s_relu[0] + s_relu[1] + s_relu[2] + s_relu[3];
        float es = s_err[0] + s_err[1] + s_err[2] + s_err[3];
        float as = s_abs[0] + s_abs[1] + s_abs[2] + s_abs[3];
        if (w_or[r] > 0.0f) {
            g_thresh[r] = 0.999999f - b_and[r] + rs;
            // input rounding (exact) + conservative f16 accumulation rounding
            g_bound[r]  = es + as * 0.02f + 2e-4f;
        } else {
            g_thresh[r] = __int_as_float(0x7f800000);  // +inf: never fires
            g_bound[r]  = 0.0f;
        }
    }
}

// exact fp32 recheck (guaranteed-correct slow path, ~0 hits/run)
static __device__ __noinline__ int exact_check(const float* __restrict__ x,
                                               int g_row, int rule) {
    const float4* xr = reinterpret_cast<const float4*>(x + (size_t)g_row * F_DIM);
    const float4* wr = reinterpret_cast<const float4*>(g_wexact + rule * F_DIM);
    float s = 0.0f;
    #pragma unroll 8
    for (int i = 0; i < F_DIM / 4; i++) {
        float4 a = xr[i], b = wr[i];
        s += a.x * b.x + a.y * b.y + a.z * b.z + a.w * b.w;
    }
    return s > g_thresh[rule] ? 1 : 0;
}

// ---------------- main persistent kernel ----------------
// 256 threads, 2 CTAs/SM, warp tile 64x32 (f16 acc), K-ring of 2x(K=64) chunks
__global__ void __launch_bounds__(NTHREADS, 2)
r2ntab_main(const float* __restrict__ x, const float* __restrict__ b_or,
            float* __restrict__ out, int num_tiles) {
    extern __shared__ char smem[];
    const uint32_t sbase = smem_u32(smem);
    const int tid  = threadIdx.x;
    const int lane = tid & 31;
    const int wid  = tid >> 5;     // 0..7
    const int wm   = wid >> 2;     // 0..1 : M group (64 rows)
    const int wn   = wid & 3;      // 0..3 : N group (32 rules)

    // ---- stage B (f16 rules, 512B rows, SW128) + tables, once ----
    {
        const uint4* wh4 = reinterpret_cast<const uint4*>(g_wh);
        #pragma unroll 4
        for (int i = tid; i < R_DIM * (F_DIM / 8); i += NTHREADS) {
            int r = i >> 5;
            int u = i & 31;
            uint4 v = wh4[i];
            *reinterpret_cast<uint4*>(smem + B_OFF + r * 512 + (((uint32_t)u ^ (r & 7)) << 4)) = v;
        }
        if (tid < R_DIM) {
            reinterpret_cast<float*>(smem + TH_OFF)[tid]  = g_thresh[tid];
            reinterpret_cast<float*>(smem + BND_OFF)[tid] = g_bound[tid];
        }
    }
    const float bor0 = b_or[0];
    const float* th_s  = reinterpret_cast<const float*>(smem + TH_OFF);
    const float* bnd_s = reinterpret_cast<const float*>(smem + BND_OFF);
    const int rule_base = wn * 32 + (lane & 3) * 2;

    // ---- ldmatrix lane addresses ----
    const int idx = lane >> 3;
    const int s3  = lane & 7;
    uint32_t a_base[4];                 // A in ring slot: row stride 128B
    #pragma unroll
    for (int mt = 0; mt < 4; mt++)
        a_base[mt] = (uint32_t)(wm * 64 + mt * 16 + (idx & 1) * 8 + s3) * 128u;
    const uint32_t a_uoff = (uint32_t)(idx >> 1);
    uint32_t b_base[2];
    #pragma unroll
    for (int p = 0; p < 2; p++)
        b_base[p] = sbase + B_OFF + (uint32_t)(wn * 32 + p * 16 + (idx >> 1) * 8 + s3) * 512u;
    const uint32_t b_uoff = (uint32_t)(idx & 1);

    int* part = reinterpret_cast<int*>(smem + PART_OFF);   // [2][128][4]

    // ---- chunk loader invariants: thread -> (q, r0); rows r0+16j, j=0..7 ----
    const int q  = tid & 15;            // float4 index within 64-float chunk row
    const int r0 = tid >> 4;            // 0..15 (row&7 == r0&7 for all j)
    const uint32_t stc = (uint32_t)(((((uint32_t)(q >> 1)) ^ (r0 & 7)) << 4) +
                                    ((uint32_t)(q & 1) << 3));
    const float4* xp = reinterpret_cast<const float4*>(x);

    const int t0 = blockIdx.x;
    float4 buf[8];
    // ---- prologue: chunk(t0,0) -> ring0 ; chunk(t0,1) -> buf ----
    {
        #pragma unroll
        for (int j = 0; j < 8; j++) {
            int row = r0 + 16 * j;
            buf[j] = xp[(size_t)(t0 * TILE_M + row) * 64 + 0 * 16 + q];
        }
        #pragma unroll
        for (int j = 0; j < 8; j++) {
            int row = r0 + 16 * j;
            __half2 h0 = __floats2half2_rn(buf[j].x, buf[j].y);
            __half2 h1 = __floats2half2_rn(buf[j].z, buf[j].w);
            uint2 val;
            val.x = *reinterpret_cast<uint32_t*>(&h0);
            val.y = *reinterpret_cast<uint32_t*>(&h1);
            *reinterpret_cast<uint2*>(smem + RING_OFF + row * 128 + stc) = val;
        }
        #pragma unroll
        for (int j = 0; j < 8; j++) {
            int row = r0 + 16 * j;
            buf[j] = xp[(size_t)(t0 * TILE_M + row) * 64 + 1 * 16 + q];
        }
    }
    __syncthreads();   // B + ring0 visible

    int it = 0;
    for (int t = t0; t < num_tiles; t += NCTAS, it++) {
        const int par = it & 1;
        uint32_t acc[4][4][2];
        #pragma unroll
        for (int mt = 0; mt < 4; mt++)
            #pragma unroll
            for (int nt = 0; nt < 4; nt++) { acc[mt][nt][0] = 0u; acc[mt][nt][1] = 0u; }

        #pragma unroll
        for (int cc = 0; cc < 4; cc++) {
            // STS chunk(cur+1) from buf -> ring[(cc+1)&1]
            const bool v1 = (cc < 3) || (t + NCTAS < num_tiles);
            if (v1) {
                char* slot1 = smem + RING_OFF + ((cc + 1) & 1) * SLOT_BYTES;
                #pragma unroll
                for (int j = 0; j < 8; j++) {
                    int row = r0 + 16 * j;
                    __half2 h0 = __floats2half2_rn(buf[j].x, buf[j].y);
                    __half2 h1 = __floats2half2_rn(buf[j].z, buf[j].w);
                    uint2 val;
                    val.x = *reinterpret_cast<uint32_t*>(&h0);
                    val.y = *reinterpret_cast<uint32_t*>(&h1);
                    *reinterpret_cast<uint2*>(slot1 + row * 128 + stc) = val;
                }
            }
            // issue LDG for chunk(cur+2)
            {
                int t2 = (cc < 2) ? t : t + NCTAS;
                int c2 = (cc < 2) ? cc + 2 : cc - 2;
                if (t2 < num_tiles) {
                    #pragma unroll
                    for (int j = 0; j < 8; j++) {
                        int row = r0 + 16 * j;
                        buf[j] = xp[(size_t)(t2 * TILE_M + row) * 64 + c2 * 16 + q];
                    }
                }
            }
            // mma: 4 k-steps on ring[cc&1]
            const uint32_t aslot = sbase + RING_OFF + (cc & 1) * SLOT_BYTES;
            #pragma unroll
            for (int ktl = 0; ktl < 4; ktl++) {
                const int kt = cc * 4 + ktl;          // tile-local k-step for B
                uint32_t bf[4][2];
                #pragma unroll
                for (int p = 0; p < 2; p++) {
                    uint32_t addr = b_base[p] + ((((uint32_t)(2 * kt) + b_uoff) ^ s3) << 4);
                    ldmatrix_x4(bf[2 * p][0], bf[2 * p][1],
                                bf[2 * p + 1][0], bf[2 * p + 1][1], addr);
                }
                #pragma unroll
                for (int mt = 0; mt < 4; mt++) {
                    uint32_t a0, a1, a2, a3;
                    uint32_t addr = aslot + a_base[mt] +
                                    ((((uint32_t)(2 * ktl) + a_uoff) ^ s3) << 4);
                    ldmatrix_x4(a0, a1, a2, a3, addr);
                    #pragma unroll
                    for (int nt = 0; nt < 4; nt++)
                        mma_f16(acc[mt][nt], a0, a1, a2, a3, bf[nt][0], bf[nt][1]);
                }
            }
            // epilogue on last chunk of the tile (before the step sync)
            if (cc == 3) {
                #pragma unroll
                for (int mt = 0; mt < 4; mt++) {
                    int rA = wm * 64 + mt * 16 + (lane >> 2);
                    int rB = rA + 8;
                    int cA = 0, cB = 0;
                    #pragma unroll
                    for (int nt = 0; nt < 4; nt++) {
                        float2 lo = __half22float2(*reinterpret_cast<__half2*>(&acc[mt][nt][0]));
                        float2 hi = __half22float2(*reinterpret_cast<__half2*>(&acc[mt][nt][1]));
                        #pragma unroll
                        for (int c = 0; c < 2; c++) {
                            const int rule = rule_base + nt * 8 + c;
                            const float thv  = th_s[rule];
                            const float bndv = bnd_s[rule];
                            float dA = (c ? lo.y : lo.x) - thv;
                            float dB = (c ? hi.y : hi.x) - thv;
                            if (fabsf(dA) <= bndv)
                                cA += exact_check(x, t * TILE_M + rA, rule);
                            else
                                cA += (dA > 0.0f) ? 1 : 0;
                            if (fabsf(dB) <= bndv)
                                cB += exact_check(x, t * TILE_M + rB, rule);
                            else
                                cB += (dB > 0.0f) ? 1 : 0;
                        }
                    }
                    cA += __shfl_xor_sync(0xffffffffu, cA, 1);
                    cA += __shfl_xor_sync(0xffffffffu, cA, 2);
                    cB += __shfl_xor_sync(0xffffffffu, cB, 1);
                    cB += __shfl_xor_sync(0xffffffffu, cB, 2);
                    if ((lane & 3) == 0) {
                        part[par * 512 + rA * 4 + wn] = cA;
                        part[par * 512 + rB * 4 + wn] = cB;
                    }
                }
            }
            __syncthreads();   // ring handoff (+ partials on cc==3)
        }

        if (tid < TILE_M) {
            int4 qv = *reinterpret_cast<int4*>(&part[par * 512 + tid * 4]);
            out[t * TILE_M + tid] = (float)(qv.x + qv.y + qv.z + qv.w) + bor0;
        }
        // part parity ping-pong: this slot is rewritten only after 4 more syncs.
    }
}

extern "C" void kernel_launch(void* const* d_in, const int* in_sizes, int n_in,
                              void* d_out, int out_size) {
    const float* x        = (const float*)d_in[0];
    const float* w_cancel = (const float*)d_in[1];
    const float* w_and    = (const float*)d_in[2];
    const float* b_and    = (const float*)d_in[3];
    const float* w_or     = (const float*)d_in[4];
    const float* b_or     = (const float*)d_in[5];
    float* out = (float*)d_out;

    const int B_total   = in_sizes[0] / F_DIM;   // 131072
    const int num_tiles = B_total / TILE_M;      // 1024

    cudaFuncSetAttribute(r2ntab_main, cudaFuncAttributeMaxDynamicSharedMemorySize, SMEM_TOTAL);

    r2ntab_prep<<<R_DIM, 128>>>(w_cancel, w_and, b_and, w_or);
    r2ntab_main<<<NCTAS, NTHREADS, SMEM_TOTAL>>>(x, b_or, out, num_tiles);
    (void)n_in; (void)out_size;
}

// round 14
// speedup vs baseline: 1.4830x; 1.3004x over previous
#include <cuda_runtime.h>
#include <cuda_fp16.h>
#include <cstdint>
#include <cstddef>

// R2Ntab: B=131072, F=256, R=128, O=1
#define F_DIM 256
#define R_DIM 128
#define TILE_M 128
#define GRID_CTAS 148
#define NTHREADS 512      // warps 0-7: consumers (GEMM), warps 8-15: producers (load)

// ---------------- device scratch (no allocs allowed) ----------------
__device__ __align__(16) float  g_wexact[R_DIM * F_DIM]; // exact masked weights
__device__ __align__(16) __half g_wh[R_DIM * F_DIM];     // f16 masked weights [r][f]
__device__ float g_thresh[R_DIM];  // fires iff dot > thresh (inf if OR-gate off)
__device__ float g_bound[R_DIM];   // guaranteed |f16dot - exact| bound

// ---------------- helpers ----------------
static __device__ __forceinline__ uint32_t smem_u32(const void* p) {
    uint32_t a;
    asm("{ .reg .u64 t; cvta.to.shared.u64 t, %1; cvt.u32.u64 %0, t; }" : "=r"(a) : "l"(p));
    return a;
}

static __device__ __forceinline__ void ldmatrix_x4(uint32_t& r0, uint32_t& r1,
                                                   uint32_t& r2, uint32_t& r3,
                                                   uint32_t addr) {
    asm volatile("ldmatrix.sync.aligned.m8n8.x4.shared.b16 {%0,%1,%2,%3}, [%4];"
                 : "=r"(r0), "=r"(r1), "=r"(r2), "=r"(r3) : "r"(addr));
}

// f16-accumulate HMMA: D(2x half2) = A*B + D
static __device__ __forceinline__ void mma_f16(uint32_t* d, uint32_t a0, uint32_t a1,
                                               uint32_t a2, uint32_t a3,
                                               uint32_t b0, uint32_t b1) {
    asm volatile(
        "mma.sync.aligned.m16n8k16.row.col.f16.f16.f16.f16 "
        "{%0,%1}, {%2,%3,%4,%5}, {%6,%7}, {%0,%1};"
        : "+r"(d[0]), "+r"(d[1])
        : "r"(a0), "r"(a1), "r"(a2), "r"(a3), "r"(b0), "r"(b1));
}

// ---------------- SMEM layout (R6 skeleton) ----------------
// A tiles (f16, swizzled): row stride 512B, 16B unit u' = u ^ (row&7)
static constexpr int A0_OFF   = 0;
static constexpr int A_BYTES  = TILE_M * F_DIM * 2;    // 65536
static constexpr int A1_OFF   = A0_OFF + A_BYTES;      // 65536
static constexpr int B_OFF    = A1_OFF + A_BYTES;      // 131072
static constexpr int B_BYTES  = R_DIM * F_DIM * 2;     // 65536
static constexpr int PART_OFF = B_OFF + B_BYTES;       // 196608  [2][128][4] ints
static constexpr int TH_OFF   = PART_OFF + 2 * TILE_M * 4 * 4;   // 200704
static constexpr int BND_OFF  = TH_OFF + R_DIM * 4;              // 201216
static constexpr int SMEM_TOTAL = BND_OFF + R_DIM * 4;           // 201728

// ---------------- precompute: mask, f16 weights, thresholds, bounds (R13) --------
__global__ void r2ntab_prep(const float* __restrict__ w_cancel,
                            const float* __restrict__ w_and,
                            const float* __restrict__ b_and,
                            const float* __restrict__ w_or) {
    __shared__ float s_relu[4], s_err[4], s_abs[4];
    const int r = blockIdx.x;
    const int t = threadIdx.x;          // 0..127
    float w0, w1;
    {
        int f0 = t, f1 = t + 128;
        w0 = (w_cancel[f0] < 0.0f) ? 0.0f : w_and[r * F_DIM + f0];
        w1 = (w_cancel[f1] < 0.0f) ? 0.0f : w_and[r * F_DIM + f1];
        g_wexact[r * F_DIM + f0] = w0;
        g_wexact[r * F_DIM + f1] = w1;
    }
    __half h0 = __float2half_rn(w0), h1 = __float2half_rn(w1);
    g_wh[r * F_DIM + t]       = h0;
    g_wh[r * F_DIM + t + 128] = h1;
    float relu = fmaxf(w0, 0.0f) + fmaxf(w1, 0.0f);
    float err  = fabsf(w0 - __half2float(h0)) + fabsf(w1 - __half2float(h1));
    float absh = fabsf(__half2float(h0)) + fabsf(__half2float(h1));
    #pragma unroll
    for (int s = 16; s > 0; s >>= 1) {
        relu += __shfl_xor_sync(0xffffffffu, relu, s);
        err  += __shfl_xor_sync(0xffffffffu, err, s);
        absh += __shfl_xor_sync(0xffffffffu, absh, s);
    }
    if ((t & 31) == 0) { s_relu[t >> 5] = relu; s_err[t >> 5] = err; s_abs[t >> 5] = absh; }
    __syncthreads();
    if (t == 0) {
        float rs = s_relu[0] + s_relu[1] + s_relu[2] + s_relu[3];
        float es = s_err[0] + s_err[1] + s_err[2] + s_err[3];
        float as = s_abs[0] + s_abs[1] + s_abs[2] + s_abs[3];
        if (w_or[r] > 0.0f) {
            g_thresh[r] = 0.999999f - b_and[r] + rs;
            g_bound[r]  = es + as * 0.02f + 2e-4f;   // f16 weight + accumulation slack
        } else {
            g_thresh[r] = __int_as_float(0x7f800000);  // +inf: never fires
            g_bound[r]  = 0.0f;
        }
    }
}

// ---------------- tile loader: gmem fp32 -> f16 swizzled smem (256 threads) -------
static __device__ __forceinline__ void load_tile(const float* __restrict__ x,
                                                 int tile, char* __restrict__ abase,
                                                 int ptid) {
    const float4* xp = reinterpret_cast<const float4*>(x) + (size_t)tile * TILE_M * (F_DIM / 4);
    #pragma unroll 8
    for (int i = ptid; i < TILE_M * (F_DIM / 4); i += 256) {
        int row = i >> 6;
        int q   = i & 63;
        float4 v = xp[i];
        __half2 p0 = __floats2half2_rn(v.x, v.y);
        __half2 p1 = __floats2half2_rn(v.z, v.w);
        uint32_t u    = (uint32_t)(q >> 1);
        uint32_t off  = (uint32_t)row * 512u + ((u ^ (row & 7)) << 4) + ((q & 1) << 3);
        uint2 val;
        val.x = *reinterpret_cast<uint32_t*>(&p0);
        val.y = *reinterpret_cast<uint32_t*>(&p1);
        *reinterpret_cast<uint2*>(abase + off) = val;
    }
}

// exact fp32 recheck (guaranteed-correct slow path, ~0 hits/run)
static __device__ __noinline__ int exact_check(const float* __restrict__ x,
                                               int g_row, int rule) {
    const float4* xr = reinterpret_cast<const float4*>(x + (size_t)g_row * F_DIM);
    const float4* wr = reinterpret_cast<const float4*>(g_wexact + rule * F_DIM);
    float s = 0.0f;
    #pragma unroll 8
    for (int i = 0; i < F_DIM / 4; i++) {
        float4 a = xr[i], b = wr[i];
        s += a.x * b.x + a.y * b.y + a.z * b.z + a.w * b.w;
    }
    return s > g_thresh[rule] ? 1 : 0;
}

// ---------------- main persistent kernel: warp-specialized ----------------
__global__ void __launch_bounds__(NTHREADS, 1)
r2ntab_main(const float* __restrict__ x, const float* __restrict__ b_or,
            float* __restrict__ out, int num_tiles) {
    extern __shared__ char smem[];
    const uint32_t sbase = smem_u32(smem);
    const int tid  = threadIdx.x;
    const int lane = tid & 31;
    const int wid  = tid >> 5;             // 0..15
    const bool consumer = (wid < 8);
    const int wm   = (wid >> 2) & 1;       // consumer: 0..1 : M group (64 rows)
    const int wn   = wid & 3;              // consumer: 0..3 : N group (32 rules)

    // ---- stage B (f16 rules, 512B rows, swizzled) + tables, once (all threads) ----
    {
        const uint4* wh4 = reinterpret_cast<const uint4*>(g_wh);
        #pragma unroll 2
        for (int i = tid; i < R_DIM * (F_DIM / 8); i += NTHREADS) {
            int r = i >> 5;
            int u = i & 31;
            uint4 v = wh4[i];
            uint32_t off = (uint32_t)r * 512u + (((uint32_t)u ^ (r & 7)) << 4);
            *reinterpret_cast<uint4*>(smem + B_OFF + off) = v;
        }
        if (tid < R_DIM) {
            reinterpret_cast<float*>(smem + TH_OFF)[tid]  = g_thresh[tid];
            reinterpret_cast<float*>(smem + BND_OFF)[tid] = g_bound[tid];
        }
    }
    const float bor0 = b_or[0];
    const float* th_s  = reinterpret_cast<const float*>(smem + TH_OFF);
    const float* bnd_s = reinterpret_cast<const float*>(smem + BND_OFF);
    const int rule_base = wn * 32 + (lane & 3) * 2;

    // ---- ldmatrix lane addresses (consumer warps) ----
    const int idx = lane >> 3;
    const int s3  = lane & 7;
    uint32_t a_row[4];
    #pragma unroll
    for (int mt = 0; mt < 4; mt++)
        a_row[mt] = (uint32_t)(wm * 64 + mt * 16 + (idx & 1) * 8 + s3) * 512u;
    const uint32_t a_usel = (uint32_t)(idx >> 1);
    uint32_t b_row[4];
    #pragma unroll
    for (int nt = 0; nt < 4; nt++)
        b_row[nt] = sbase + B_OFF + (uint32_t)(wn * 32 + nt * 8 + s3) * 512u;
    const uint32_t b_usel = (uint32_t)(idx & 1);

    int* part = reinterpret_cast<int*>(smem + PART_OFF);   // [2][128][4]

    const int t0 = blockIdx.x;
    int cur = 0;
    if (!consumer && t0 < num_tiles)
        load_tile(x, t0, smem + A0_OFF, tid - 256);
    __syncthreads();   // B + tile0 staged

    int it = 0;
    for (int t = t0; t < num_tiles; t += GRID_CTAS, it++) {
        const int par = it & 1;

        if (consumer) {
            // ---- GEMM 128x128x256, warp tile 64x32, f16 accumulate ----
            const uint32_t abuf = sbase + (cur ? A1_OFF : A0_OFF);
            uint32_t acc[4][4][2];
            #pragma unroll
            for (int mt = 0; mt < 4; mt++)
                #pragma unroll
                for (int nt = 0; nt < 4; nt++) { acc[mt][nt][0] = 0u; acc[mt][nt][1] = 0u; }

            #pragma unroll
            for (int kt = 0; kt < 16; kt++) {
                uint32_t bf[4][2];
                #pragma unroll
                for (int p = 0; p < 2; p++) {
                    uint32_t addr = b_row[2 * p + (idx >> 1)] +
                                    ((((uint32_t)(2 * kt) + b_usel) ^ s3) << 4);
                    ldmatrix_x4(bf[2 * p][0], bf[2 * p][1],
                                bf[2 * p + 1][0], bf[2 * p + 1][1], addr);
                }
                #pragma unroll
                for (int mt = 0; mt < 4; mt++) {
                    uint32_t a0, a1, a2, a3;
                    uint32_t addr = abuf + a_row[mt] +
                                    ((((uint32_t)(2 * kt) + a_usel) ^ s3) << 4);
                    ldmatrix_x4(a0, a1, a2, a3, addr);
                    #pragma unroll
                    for (int nt = 0; nt < 4; nt++)
                        mma_f16(acc[mt][nt], a0, a1, a2, a3, bf[nt][0], bf[nt][1]);
                }
            }

            // ---- epilogue: threshold-count with exact-recheck guard ----
            #pragma unroll
            for (int mt = 0; mt < 4; mt++) {
                int rA = wm * 64 + mt * 16 + (lane >> 2);
                int rB = rA + 8;
                int cA = 0, cB = 0;
                #pragma unroll
                for (int nt = 0; nt < 4; nt++) {
                    float2 lo = __half22float2(*reinterpret_cast<__half2*>(&acc[mt][nt][0]));
                    float2 hi = __half22float2(*reinterpret_cast<__half2*>(&acc[mt][nt][1]));
                    #pragma unroll
                    for (int c = 0; c < 2; c++) {
                        const int rule = rule_base + nt * 8 + c;
                        const float thv  = th_s[rule];
                        const float bndv = bnd_s[rule];
                        float dA = (c ? lo.y : lo.x) - thv;
                        float dB = (c ? hi.y : hi.x) - thv;
                        if (fabsf(dA) <= bndv)
                            cA += exact_check(x, t * TILE_M + rA, rule);
                        else
                            cA += (dA > 0.0f) ? 1 : 0;
                        if (fabsf(dB) <= bndv)
                            cB += exact_check(x, t * TILE_M + rB, rule);
                        else
                            cB += (dB > 0.0f) ? 1 : 0;
                    }
                }
                cA += __shfl_xor_sync(0xffffffffu, cA, 1);
                cA += __shfl_xor_sync(0xffffffffu, cA, 2);
                cB += __shfl_xor_sync(0xffffffffu, cB, 1);
                cB += __shfl_xor_sync(0xffffffffu, cB, 2);
                if ((lane & 3) == 0) {
                    part[par * 512 + rA * 4 + wn] = cA;
                    part[par * 512 + rB * 4 + wn] = cB;
                }
            }
        } else {
            // ---- producer: load next tile into the other buffer ----
            const int tn = t + GRID_CTAS;
            if (tn < num_tiles)
                load_tile(x, tn, smem + (cur ? A0_OFF : A1_OFF), tid - 256);
        }

        __syncthreads();   // partials ready; next tile staged

        if (tid < TILE_M) {
            int4 qv = *reinterpret_cast<int4*>(&part[par * 512 + tid * 4]);
            out[t * TILE_M + tid] = (float)(qv.x + qv.y + qv.z + qv.w) + bor0;
        }
        cur ^= 1;
        // part parity ping-pong: slot `par` not rewritten until 2 barriers later.
    }
}

extern "C" void kernel_launch(void* const* d_in, const int* in_sizes, int n_in,
                              void* d_out, int out_size) {
    const float* x        = (const float*)d_in[0];
    const float* w_cancel = (const float*)d_in[1];
    const float* w_and    = (const float*)d_in[2];
    const float* b_and    = (const float*)d_in[3];
    const float* w_or     = (const float*)d_in[4];
    const float* b_or     = (const float*)d_in[5];
    float* out = (float*)d_out;

    const int B_total   = in_sizes[0] / F_DIM;   // 131072
    const int num_tiles = B_total / TILE_M;      // 1024

    cudaFuncSetAttribute(r2ntab_main, cudaFuncAttributeMaxDynamicSharedMemorySize, SMEM_TOTAL);

    r2ntab_prep<<<R_DIM, 128>>>(w_cancel, w_and, b_and, w_or);
    r2ntab_main<<<GRID_CTAS, NTHREADS, SMEM_TOTAL>>>(x, b_or, out, num_tiles);
    (void)n_in; (void)out_size;
}